// round 1
// baseline (speedup 1.0000x reference)
#include <cuda_runtime.h>
#include <cuda_fp16.h>
#include <math.h>

#define NEGV (-1e30f)

constexpr int C       = 256;   // symbol count (fixed by problem)
constexpr int LMAX    = 128;   // max label length
constexpr int PITCH   = 264;   // fp16 row pitch (528B = 33*16B, keeps LDS.128 aligned, kills STS conflicts on transpose fill)
constexpr int THREADS = 256;
constexpr int MAXB    = 64;

// cross-kernel scratch (device globals are the allowed scratch mechanism)
__device__ float g_f  [MAXB][C];
__device__ float g_g  [MAXB][C];
__device__ float g_a  [MAXB][LMAX];
__device__ float g_bt [MAXB][LMAX];
__device__ float g_lsf[MAXB];
__device__ float g_lsg[MAXB];

struct SmemLayout {
  __half M[C * PITCH];      // exp(trans) (or its transpose for bwd blocks), fp16: 135168 B
  float  part[8 * C];       // c-split partial sums: 8 KB
  float  p[C];              // current (scaled) forward/backward vector
  float  xt[2][C];          // double-buffered x_t tile
  float  nb[2][LMAX + 2];   // numerator alpha/beta, sentinel-padded
  float  red[8];            // per-warp partial sums for S
  int    labs[LMAX];
};

__device__ __forceinline__ float lse2(float a, float b) {
  float mx = fmaxf(a, b);
  float mn = fminf(a, b);
  return mx + log1pf(__expf(mn - mx));
}

__global__ void __launch_bounds__(THREADS, 1)
chain_kernel(const float* __restrict__ x, const float* __restrict__ trans,
             const int* __restrict__ labels, const int* __restrict__ durations,
             int T, int L)
{
  extern __shared__ char smraw[];
  SmemLayout& sm = *reinterpret_cast<SmemLayout*>(smraw);

  const int  tid = threadIdx.x;
  const int  b   = blockIdx.x >> 1;
  const bool bwd = blockIdx.x & 1;

  const int D      = durations[b];
  const int m      = D >> 1;
  const int nsteps = bwd ? (D - 1 - m) : m;   // fwd: t=1..m ; bwd: t=D-1..m+1
  const int dt     = bwd ? -1 : 1;
  int t            = bwd ? (D - 1) : 1;

  // ---- init E (fp16) in smem; bwd blocks store the transpose so both use identical inner loops
  for (int idx = tid; idx < C * C; idx += THREADS) {
    int r = idx >> 8, cl = idx & 255;
    float v = __expf(trans[idx]);               // E[r][cl]
    if (!bwd) sm.M[r * PITCH + cl] = __float2half_rn(v);   // M[c][j]  = E[c][j]
    else      sm.M[cl * PITCH + r] = __float2half_rn(v);   // M[c'][c] = E[c][c']
  }
  for (int l = tid; l < L; l += THREADS) sm.labs[l] = labels[b * L + l];

  const float* xb = x + (size_t)b * T * C;

  { // initial den vector p and first x tile
    int tp = bwd ? (D - 1) : 0;
    sm.p[tid]     = __expf(xb[(size_t)tp * C + tid]);  // fwd: f0=exp(x0); bwd: g_{D-1}∘ex_{D-1}=exp(x_{D-1})
    sm.xt[0][tid] = xb[(size_t)t * C + tid];
  }
  if (tid < LMAX + 2) { sm.nb[0][tid] = NEGV; sm.nb[1][tid] = NEGV; }
  __syncthreads();
  if (tid == 0) {
    if (!bwd) sm.nb[0][1] = xb[sm.labs[0]];  // alpha_0[0] = x[0][lab0]
    else      sm.nb[0][L] = 0.0f;            // beta_{D-1}[L-1] = 0
  }

  float logS = 0.0f;
  int   cur  = 0;

  const int lane = tid & 31;
  const int wrp  = tid >> 5;                       // c-group (8-way c split)
  const __half* Mbase = sm.M + (wrp * 32) * PITCH + lane * 8;  // 8 consecutive j per lane
  const float*  pp    = sm.p + wrp * 32;

  for (int k = 0; k < nsteps; ++k) {
    __syncthreads();  // A: p, xt[cur] ready
    const bool more = (k + 1) < nsteps;
    float pf = 0.0f;
    if (more) pf = xb[(size_t)(t + dt) * C + tid]; // prefetch next x_t, hidden behind GEMV

    // ---- GEMV: y_j = sum_c p[c] * M[c][j], fp16 M, fp32 acc
    float y0=0,y1=0,y2=0,y3=0,y4=0,y5=0,y6=0,y7=0;
    #pragma unroll
    for (int i = 0; i < 32; ++i) {
      float pc = pp[i];                            // broadcast LDS
      uint4 w = *reinterpret_cast<const uint4*>(Mbase + i * PITCH); // 8 fp16, conflict-free LDS.128
      float2 fA = __half22float2(*reinterpret_cast<const __half2*>(&w.x));
      float2 fB = __half22float2(*reinterpret_cast<const __half2*>(&w.y));
      float2 fC = __half22float2(*reinterpret_cast<const __half2*>(&w.z));
      float2 fD = __half22float2(*reinterpret_cast<const __half2*>(&w.w));
      y0 = fmaf(pc, fA.x, y0);  y1 = fmaf(pc, fA.y, y1);
      y2 = fmaf(pc, fB.x, y2);  y3 = fmaf(pc, fB.y, y3);
      y4 = fmaf(pc, fC.x, y4);  y5 = fmaf(pc, fC.y, y5);
      y6 = fmaf(pc, fD.x, y6);  y7 = fmaf(pc, fD.y, y7);
    }
    {
      float* pr = sm.part + wrp * C + lane * 8;
      float4* p4 = reinterpret_cast<float4*>(pr);
      p4[0] = make_float4(y0, y1, y2, y3);
      p4[1] = make_float4(y4, y5, y6, y7);
    }
    __syncthreads();  // B: partials visible

    float yv = 0.0f;
    #pragma unroll
    for (int g2 = 0; g2 < 8; ++g2) yv += sm.part[g2 * C + tid];
    if (!bwd) yv *= __expf(sm.xt[cur][tid]);       // fwd applies ex_t AFTER the GEMV

    float ws = yv;
    #pragma unroll
    for (int o = 16; o; o >>= 1) ws += __shfl_xor_sync(0xffffffffu, ws, o);
    if (lane == 0) sm.red[wrp] = ws;

    // ---- numerator update (log domain), overlapped before sync C
    float nnew = 0.0f;
    const bool donum = tid < L;
    if (donum) {
      int l = tid;
      if (!bwd) {
        float e = sm.xt[cur][sm.labs[l]];
        nnew = lse2(sm.nb[cur][l + 1], sm.nb[cur][l]) + e;   // lse(a[l], a[l-1]) + e_t[l]
      } else {
        float v0 = sm.nb[cur][l + 1] + sm.xt[cur][sm.labs[l]];
        float v1 = NEGV;
        if (l + 1 < L) v1 = sm.nb[cur][l + 2] + sm.xt[cur][sm.labs[l + 1]];
        nnew = lse2(v0, v1);
      }
    }
    __syncthreads();  // C: red visible

    float S = 0.0f;
    #pragma unroll
    for (int g2 = 0; g2 < 8; ++g2) S += sm.red[g2];
    float rcp = 1.0f / S;                         // exact div; pairs exactly with logf(S)
    float pv  = yv * rcp;
    if (bwd && more) pv *= __expf(pf);            // bwd applies ex_{t-1} BEFORE next GEMV
    sm.p[tid] = pv;
    if (donum) sm.nb[cur ^ 1][tid + 1] = nnew;
    if (more)  sm.xt[cur ^ 1][tid] = pf;
    if (tid == 0) logS += logf(S);

    cur ^= 1;
    t   += dt;
  }
  __syncthreads();

  if (!bwd) {
    g_f[b][tid] = sm.p[tid];                      // \hat f_m (normalized)
    if (tid < L) g_a[b][tid] = sm.nb[cur][tid + 1];
    if (tid == 0) g_lsf[b] = logS;
  } else {
    g_g[b][tid] = sm.p[tid];                      // \hat g_m (no ex on final step)
    if (tid < L) g_bt[b][tid] = sm.nb[cur][tid + 1];
    if (tid == 0) g_lsg[b] = logS;
  }
}

__global__ void combine_kernel(const int* __restrict__ durations, int B, int L,
                               float* __restrict__ out, int out_size)
{
  __shared__ float sc[MAXB];
  int b = threadIdx.x;
  float v = 0.0f;
  if (b < B) {
    float dot = 0.0f;
    for (int c = 0; c < C; ++c) dot += g_f[b][c] * g_g[b][c];
    float den = logf(dot) + g_lsf[b] + g_lsg[b];

    float mx = -INFINITY;
    for (int l = 0; l < L; ++l) mx = fmaxf(mx, g_a[b][l] + g_bt[b][l]);
    float s = 0.0f;
    for (int l = 0; l < L; ++l) s += expf(g_a[b][l] + g_bt[b][l] - mx);
    float num = mx + logf(s);
    v = num - den;
  }
  if (b < MAXB) sc[b] = v;
  __syncthreads();
  if (b == 0) {
    float tot = 0.0f;
    for (int i = 0; i < B; ++i) tot += sc[i];   // fixed-order => deterministic
    long long fr = 0;
    for (int i = 0; i < B; ++i) fr += durations[i];
    out[0] = tot;
    if (out_size > 1) out[1] = (float)fr;
    if (out_size > 2) out[2] = (float)fr;
  }
}

extern "C" void kernel_launch(void* const* d_in, const int* in_sizes, int n_in,
                              void* d_out, int out_size)
{
  const float* x      = (const float*)d_in[0];
  const float* trans  = (const float*)d_in[1];
  const int*   labels = (const int*)d_in[2];
  const int*   dur    = (const int*)d_in[3];

  int B = in_sizes[3];
  int L = in_sizes[2] / B;
  int T = in_sizes[0] / (B * C);

  size_t smem = sizeof(SmemLayout);
  cudaFuncSetAttribute(chain_kernel, cudaFuncAttributeMaxDynamicSharedMemorySize, (int)smem);

  chain_kernel<<<2 * B, THREADS, smem>>>(x, trans, labels, dur, T, L);
  combine_kernel<<<1, MAXB>>>(dur, B, L, (float*)d_out, out_size);
}

// round 2
// speedup vs baseline: 1.0533x; 1.0533x over previous
#include <cuda_runtime.h>
#include <cuda_bf16.h>
#include <math.h>

#define NEGV (-1e30f)

constexpr int C       = 256;
constexpr int LMAX    = 128;
constexpr int THREADS = 512;   // 16 warps, 16-way c-split
constexpr int NW      = 16;
constexpr int PITCH   = 264;   // bf16 elems per row (528B, keeps LDS.128 conflict-free)
constexpr int MAXB    = 64;

__device__ float g_f  [MAXB][C];
__device__ float g_g  [MAXB][C];
__device__ float g_a  [MAXB][LMAX];
__device__ float g_bt [MAXB][LMAX];
__device__ float g_lsf[MAXB];
__device__ float g_lsg[MAXB];

struct SmemLayout {
  unsigned short M[C * PITCH];   // exp(trans) as bf16 bits (transposed for bwd blocks): 135168 B
  float part[NW * C];            // 16 KB partials
  float p[C];                    // current (lag-normalized) vector w
  float xt[2][C];                // double-buffered x_t (numerator reads at labs[l])
  float nb[2][LMAX + 2];         // numerator alpha/beta, sentinel padded
  float red[8];                  // per-warp (warps 0-7) sums of w
  int   labs[LMAX];
};

__device__ __forceinline__ float lse2(float a, float b) {
  float mx = fmaxf(a, b);
  float mn = fminf(a, b);
  return mx + log1pf(__expf(mn - mx));
}

__device__ __forceinline__ float bf_lo(unsigned int w) { return __uint_as_float(w << 16); }
__device__ __forceinline__ float bf_hi(unsigned int w) { return __uint_as_float(w & 0xffff0000u); }

__global__ void __launch_bounds__(THREADS, 1)
chain_kernel(const float* __restrict__ x, const float* __restrict__ trans,
             const int* __restrict__ labels, const int* __restrict__ durations,
             int T, int L)
{
  extern __shared__ char smraw[];
  SmemLayout& sm = *reinterpret_cast<SmemLayout*>(smraw);

  const int  tid = threadIdx.x;
  const int  b   = blockIdx.x >> 1;
  const bool bwd = blockIdx.x & 1;
  const int  lane = tid & 31;
  const int  wrp  = tid >> 5;

  const int D      = durations[b];
  const int m      = D >> 1;
  const int nsteps = bwd ? (D - 1 - m) : m;
  const int dt     = bwd ? -1 : 1;
  int t            = bwd ? (D - 1) : 1;

  // ---- init M = exp(trans) as bf16 (bwd blocks store transpose) ----
  for (int idx = tid; idx < C * C; idx += THREADS) {
    int r = idx >> 8, cl = idx & 255;
    float v = __expf(trans[idx]);
    unsigned short hs = __bfloat16_as_ushort(__float2bfloat16(v));
    if (!bwd) sm.M[r * PITCH + cl] = hs;
    else      sm.M[cl * PITCH + r] = hs;
  }
  for (int l = tid; l < L; l += THREADS) sm.labs[l] = labels[b * L + l];

  const float* xb = x + (size_t)b * T * C;

  float xcur = 0.0f;     // register-carried x_t for this thread's symbol (fwd ex factor)
  if (tid < C) {
    int tp = bwd ? (D - 1) : 0;
    float w0 = __expf(xb[(size_t)tp * C + tid]);
    sm.p[tid] = w0;
    xcur      = xb[(size_t)t * C + tid];
    sm.xt[0][tid] = xcur;
    // init red = per-warp sums of w0 (warps 0-7)
    float ws = w0;
    #pragma unroll
    for (int o = 16; o; o >>= 1) ws += __shfl_xor_sync(0xffffffffu, ws, o);
    if (lane == 0) sm.red[wrp] = ws;
  }
  if (tid < LMAX + 2) { sm.nb[0][tid] = NEGV; sm.nb[1][tid] = NEGV; }
  __syncthreads();
  if (tid == 0) {
    if (!bwd) sm.nb[0][1] = xb[sm.labs[0]];
    else      sm.nb[0][L] = 0.0f;
  }

  float logS = 0.0f;
  int   cur  = 0;

  const float*          pp    = sm.p + wrp * NW;           // this warp's 16 c values
  const unsigned short* Mbase = sm.M + (wrp * NW) * PITCH + lane * 8;

  for (int k = 0; k < nsteps; ++k) {
    __syncthreads();  // A: p, red, xt[cur], nb[cur] ready
    const bool more = (k + 1) < nsteps;

    float pf = 0.0f;
    if (more && tid < C) pf = xb[(size_t)(t + dt) * C + tid];  // prefetch next x_t

    float S = 0.0f;
    if (tid < C) {   // lagged normalizer: sum of previous w (warp-granular guard)
      #pragma unroll
      for (int g = 0; g < 8; ++g) S += sm.red[g];
    }

    // ---- GEMV: y_j = sum_c w[c] * M[c][j]   (bf16 M, ALU expand, fp32 FMA)
    float y0=0,y1=0,y2=0,y3=0,y4=0,y5=0,y6=0,y7=0;
    #pragma unroll
    for (int i = 0; i < NW; ++i) {
      float pc = pp[i];
      uint4 wv = *reinterpret_cast<const uint4*>(Mbase + i * PITCH);
      y0 = fmaf(pc, bf_lo(wv.x), y0);  y1 = fmaf(pc, bf_hi(wv.x), y1);
      y2 = fmaf(pc, bf_lo(wv.y), y2);  y3 = fmaf(pc, bf_hi(wv.y), y3);
      y4 = fmaf(pc, bf_lo(wv.z), y4);  y5 = fmaf(pc, bf_hi(wv.z), y5);
      y6 = fmaf(pc, bf_lo(wv.w), y6);  y7 = fmaf(pc, bf_hi(wv.w), y7);
    }
    {
      float4* p4 = reinterpret_cast<float4*>(sm.part + wrp * C + lane * 8);
      p4[0] = make_float4(y0, y1, y2, y3);
      p4[1] = make_float4(y4, y5, y6, y7);
    }
    __syncthreads();  // B: partials visible

    if (tid < C) {
      float yv = 0.0f;
      #pragma unroll
      for (int g = 0; g < NW; ++g) yv += sm.part[g * C + tid];

      float rs = 1.0f / S;
      float wnew;
      if (!bwd) {
        wnew = yv * __expf(xcur) * rs;          // fwd folds ex_t after GEMV
      } else {
        wnew = yv * rs;
        if (more) wnew *= __expf(pf);           // bwd folds ex_{t-1} before next GEMV
      }
      sm.p[tid] = wnew;

      float ws = wnew;                           // deferred normalizer for NEXT step
      #pragma unroll
      for (int o = 16; o; o >>= 1) ws += __shfl_xor_sync(0xffffffffu, ws, o);
      if (lane == 0) sm.red[wrp] = ws;

      if (more) sm.xt[cur ^ 1][tid] = pf;
      xcur = pf;
    }

    // ---- numerator (log domain), same phase
    if (tid < L) {
      int l = tid;
      float nnew;
      if (!bwd) {
        float e = sm.xt[cur][sm.labs[l]];
        nnew = lse2(sm.nb[cur][l + 1], sm.nb[cur][l]) + e;
      } else {
        float v0 = sm.nb[cur][l + 1] + sm.xt[cur][sm.labs[l]];
        float v1 = NEGV;
        if (l + 1 < L) v1 = sm.nb[cur][l + 2] + sm.xt[cur][sm.labs[l + 1]];
        nnew = lse2(v0, v1);
      }
      sm.nb[cur ^ 1][l + 1] = nnew;
    }

    if (tid == 0) logS += logf(S);

    cur ^= 1;
    t   += dt;
  }
  __syncthreads();

  // final normalization of the unnormalized w
  float Sf = 0.0f;
  #pragma unroll
  for (int g = 0; g < 8; ++g) Sf += sm.red[g];

  if (!bwd) {
    if (tid < C) g_f[b][tid] = sm.p[tid] / Sf;
    if (tid < L) g_a[b][tid] = sm.nb[cur][tid + 1];
    if (tid == 0) g_lsf[b] = logS + logf(Sf);
  } else {
    if (tid < C) g_g[b][tid] = sm.p[tid] / Sf;
    if (tid < L) g_bt[b][tid] = sm.nb[cur][tid + 1];
    if (tid == 0) g_lsg[b] = logS + logf(Sf);
  }
}

__global__ void __launch_bounds__(1024, 1)
combine_kernel(const int* __restrict__ durations, int B, int L,
               float* __restrict__ out, int out_size)
{
  __shared__ float sc[MAXB];
  const int lane = threadIdx.x & 31;
  const int w    = threadIdx.x >> 5;   // 32 warps

  for (int b = w; b < B; b += 32) {
    float dot = 0.0f;
    for (int c = lane; c < C; c += 32) dot += g_f[b][c] * g_g[b][c];
    #pragma unroll
    for (int o = 16; o; o >>= 1) dot += __shfl_xor_sync(0xffffffffu, dot, o);

    float mx = -INFINITY;
    for (int l = lane; l < L; l += 32) mx = fmaxf(mx, g_a[b][l] + g_bt[b][l]);
    #pragma unroll
    for (int o = 16; o; o >>= 1) mx = fmaxf(mx, __shfl_xor_sync(0xffffffffu, mx, o));

    float s = 0.0f;
    for (int l = lane; l < L; l += 32) s += expf(g_a[b][l] + g_bt[b][l] - mx);
    #pragma unroll
    for (int o = 16; o; o >>= 1) s += __shfl_xor_sync(0xffffffffu, s, o);

    if (lane == 0) {
      float num = mx + logf(s);
      float den = logf(dot) + g_lsf[b] + g_lsg[b];
      sc[b] = num - den;
    }
  }
  __syncthreads();
  if (threadIdx.x == 0) {
    float tot = 0.0f;
    for (int i = 0; i < B; ++i) tot += sc[i];     // fixed order => deterministic
    long long fr = 0;
    for (int i = 0; i < B; ++i) fr += durations[i];
    out[0] = tot;
    if (out_size > 1) out[1] = (float)fr;
    if (out_size > 2) out[2] = (float)fr;
  }
}

extern "C" void kernel_launch(void* const* d_in, const int* in_sizes, int n_in,
                              void* d_out, int out_size)
{
  const float* x      = (const float*)d_in[0];
  const float* trans  = (const float*)d_in[1];
  const int*   labels = (const int*)d_in[2];
  const int*   dur    = (const int*)d_in[3];

  int B = in_sizes[3];
  int L = in_sizes[2] / B;
  int T = in_sizes[0] / (B * C);

  size_t smem = sizeof(SmemLayout);
  cudaFuncSetAttribute(chain_kernel, cudaFuncAttributeMaxDynamicSharedMemorySize, (int)smem);

  chain_kernel<<<2 * B, THREADS, smem>>>(x, trans, labels, dur, T, L);
  combine_kernel<<<1, 1024>>>(dur, B, L, (float*)d_out, out_size);
}